// round 8
// baseline (speedup 1.0000x reference)
#include <cuda_runtime.h>

// Problem constants (shapes are fixed by the dataset)
#define NMAX 50000
#define EMAX 800000
#define F1 128
#define F2 64

// ---------------- scratch (static __device__ globals; no allocation) --------
__device__ int   g_cnt[NMAX];
__device__ int   g_cursor[NMAX];
__device__ int   g_rowptr[NMAX + 1];
__device__ int   g_col[EMAX];
__device__ float g_dinv[NMAX];
__device__ float g_invcnt[NMAX];

__device__ float g_p [NMAX * F1];   // x @ W1l
__device__ float g_q [NMAX * F1];   // x @ W1r
__device__ float g_h [NMAX * F1];   // layer-1 output (relu)
__device__ float g_u [NMAX * F2];   // h @ W2l
__device__ float g_v [NMAX * F2];   // h @ W2r
__device__ float g_z [NMAX * F2];   // softmax output
__device__ float g_xw[NMAX * F2];   // z @ Wg

__device__ __forceinline__ int clampi(int v, int lo, int hi) {
    return v < lo ? lo : (v > hi ? hi : v);
}

// ---------------- CSR build -------------------------------------------------
__global__ void k_zero(int n) {
    int i = blockIdx.x * blockDim.x + threadIdx.x;
    if (i < n) { g_cnt[i] = 0; g_cursor[i] = 0; }
}

// edge_index is int32 (JAX x64 disabled: jnp.int64 request silently yields int32)
__global__ void k_count(const int* __restrict__ ei, int E, int n) {
    int e = blockIdx.x * blockDim.x + threadIdx.x;
    if (e < E) {
        int d = clampi(ei[E + e], 0, n - 1);   // clamp: never trap on bad dtype
        atomicAdd(&g_cnt[d], 1);
    }
}

// single-block exclusive scan of g_cnt -> g_rowptr
__global__ void k_scan(int n) {
    __shared__ int wsums[32];
    __shared__ int sh_carry, sh_total;
    int tid = threadIdx.x;
    if (tid == 0) sh_carry = 0;
    __syncthreads();
    for (int base = 0; base < n; base += 1024) {
        int i = base + tid;
        int v = (i < n) ? g_cnt[i] : 0;
        int incl = v;
        #pragma unroll
        for (int off = 1; off < 32; off <<= 1) {
            int y = __shfl_up_sync(0xffffffffu, incl, off);
            if ((tid & 31) >= off) incl += y;
        }
        if ((tid & 31) == 31) wsums[tid >> 5] = incl;
        __syncthreads();
        if (tid < 32) {
            int w = wsums[tid];
            int wi = w;
            #pragma unroll
            for (int off = 1; off < 32; off <<= 1) {
                int y = __shfl_up_sync(0xffffffffu, wi, off);
                if (tid >= off) wi += y;
            }
            wsums[tid] = wi - w;           // exclusive warp offset
            if (tid == 31) sh_total = wi;  // block total
        }
        __syncthreads();
        if (i < n) g_rowptr[i] = sh_carry + wsums[tid >> 5] + incl - v;
        __syncthreads();
        if (tid == 0) sh_carry += sh_total;
        __syncthreads();
    }
    if (tid == 0) g_rowptr[n] = sh_carry;
}

__global__ void k_nodeprep(int n) {
    int i = blockIdx.x * blockDim.x + threadIdx.x;
    if (i < n) {
        int c = g_cnt[i];
        g_invcnt[i] = 1.0f / (float)(c > 1 ? c : 1);
        g_dinv[i]   = rsqrtf((float)(c + 1));   // GCN deg includes self-loop
    }
}

__global__ void k_fill(const int* __restrict__ ei, int E, int n) {
    int e = blockIdx.x * blockDim.x + threadIdx.x;
    if (e < E) {
        int s = clampi(ei[e],     0, n - 1);
        int d = clampi(ei[E + e], 0, n - 1);
        int pos = atomicAdd(&g_cursor[d], 1);
        g_col[g_rowptr[d] + pos] = s;
    }
}

// ---------------- SGEMM body: C[NR,M] = A[NR,K] @ B[K,M], row-major ---------
template<int BM, int BN, int BK, int TM, int TN>
__device__ __forceinline__
void sgemm_body(const float* __restrict__ A, const float* __restrict__ B,
                float* __restrict__ C, int NR, int K, int M) {
    __shared__ float As[BK][BM + 1];
    __shared__ float Bs[BK][BN];
    const int NT = (BM / TM) * (BN / TN);
    int tid = threadIdx.x;
    int tx = tid % (BN / TN);
    int ty = tid / (BN / TN);
    int rowBase = blockIdx.y * BM;
    int colBase = blockIdx.x * BN;

    float acc[TM][TN];
    #pragma unroll
    for (int i = 0; i < TM; i++)
        #pragma unroll
        for (int j = 0; j < TN; j++) acc[i][j] = 0.f;

    for (int k0 = 0; k0 < K; k0 += BK) {
        for (int i = tid; i < BM * BK; i += NT) {
            int m = i / BK, k = i % BK;
            int r = rowBase + m;
            As[k][m] = (r < NR) ? A[(size_t)r * K + k0 + k] : 0.f;
        }
        for (int i = tid; i < BK * BN; i += NT) {
            int k = i / BN, nn = i % BN;
            Bs[k][nn] = B[(size_t)(k0 + k) * M + colBase + nn];
        }
        __syncthreads();
        #pragma unroll
        for (int kk = 0; kk < BK; kk++) {
            float a[TM], b[TN];
            #pragma unroll
            for (int t = 0; t < TM; t++) a[t] = As[kk][ty * TM + t];
            #pragma unroll
            for (int t = 0; t < TN; t++) b[t] = Bs[kk][tx * TN + t];
            #pragma unroll
            for (int i = 0; i < TM; i++)
                #pragma unroll
                for (int j = 0; j < TN; j++)
                    acc[i][j] = fmaf(a[i], b[j], acc[i][j]);
        }
        __syncthreads();
    }
    #pragma unroll
    for (int i = 0; i < TM; i++) {
        int r = rowBase + ty * TM + i;
        if (r < NR) {
            #pragma unroll
            for (int j = 0; j < TN; j++)
                C[(size_t)r * M + colBase + tx * TN + j] = acc[i][j];
        }
    }
}

// GEMM wrappers: scratch buffers bound as direct __device__ symbol references.
__global__ __launch_bounds__(256)
void k_gemm_x(const float* __restrict__ A, const float* __restrict__ W,
              int which, int NR) {
    float* C = which ? g_q : g_p;
    sgemm_body<64, 64, 16, 4, 4>(A, W, C, NR, F1, F1);
}

__global__ __launch_bounds__(256)
void k_gemm_h(const float* __restrict__ W, int which, int NR) {
    float* C = which ? g_v : g_u;
    sgemm_body<64, 64, 16, 4, 4>(g_h, W, C, NR, F1, F2);
}

__global__ __launch_bounds__(256)
void k_gemm_z(const float* __restrict__ W, int NR) {
    sgemm_body<64, 64, 16, 4, 4>(g_z, W, g_xw, NR, F2, F2);
}

// ---------------- aggregation kernels (one block per node) ------------------
// h = relu(agg(p)/cnt + b1l + q)
__global__ void k_agg1(const float* __restrict__ b1l) {
    int i = blockIdx.x;
    int f = threadIdx.x;
    int beg = g_rowptr[i], end = g_rowptr[i + 1];
    float s = 0.f;
    for (int e = beg; e < end; e++) {
        int j = g_col[e];
        s += g_p[(size_t)j * F1 + f];
    }
    float h = s * g_invcnt[i] + b1l[f] + g_q[(size_t)i * F1 + f];
    g_h[(size_t)i * F1 + f] = fmaxf(h, 0.f);
}

// z = softmax(agg(u)/cnt + b2l + v)
__global__ void k_agg2(const float* __restrict__ b2l) {
    __shared__ float red[2];
    int i = blockIdx.x;
    int f = threadIdx.x;     // 0..63, 2 warps
    int beg = g_rowptr[i], end = g_rowptr[i + 1];
    float s = 0.f;
    for (int e = beg; e < end; e++)
        s += g_u[(size_t)g_col[e] * F2 + f];
    float t = s * g_invcnt[i] + b2l[f] + g_v[(size_t)i * F2 + f];

    float m = t;
    #pragma unroll
    for (int off = 16; off > 0; off >>= 1)
        m = fmaxf(m, __shfl_xor_sync(0xffffffffu, m, off));
    if ((f & 31) == 0) red[f >> 5] = m;
    __syncthreads();
    m = fmaxf(red[0], red[1]);
    float ex = expf(t - m);
    float sum = ex;
    #pragma unroll
    for (int off = 16; off > 0; off >>= 1)
        sum += __shfl_xor_sync(0xffffffffu, sum, off);
    __syncthreads();
    if ((f & 31) == 0) red[f >> 5] = sum;
    __syncthreads();
    sum = red[0] + red[1];
    g_z[(size_t)i * F2 + f] = ex / sum;
}

// out = dinv[i] * agg(dinv[j]*xw[j]) + dinv[i]^2 * xw[i] + bg
__global__ void k_agg3(const float* __restrict__ bg, float* __restrict__ out) {
    int i = blockIdx.x;
    int f = threadIdx.x;   // 0..63
    int beg = g_rowptr[i], end = g_rowptr[i + 1];
    float s = 0.f;
    for (int e = beg; e < end; e++) {
        int j = g_col[e];
        s += g_dinv[j] * g_xw[(size_t)j * F2 + f];
    }
    float di = g_dinv[i];
    out[(size_t)i * F2 + f] = di * s + di * di * g_xw[(size_t)i * F2 + f] + bg[f];
}

// ---------------- launch ----------------------------------------------------
extern "C" void kernel_launch(void* const* d_in, const int* in_sizes, int n_in,
                              void* d_out, int out_size) {
    const float* x   = (const float*)d_in[0];
    const int*   ei  = (const int*)d_in[1];      // int32 (JAX x64 disabled)
    const float* W1l = (const float*)d_in[2];
    const float* b1l = (const float*)d_in[3];
    const float* W1r = (const float*)d_in[4];
    const float* W2l = (const float*)d_in[5];
    const float* b2l = (const float*)d_in[6];
    const float* W2r = (const float*)d_in[7];
    const float* Wg  = (const float*)d_in[8];
    const float* bg  = (const float*)d_in[9];
    float* out = (float*)d_out;

    int N = in_sizes[0] / F1;
    int E = in_sizes[1] / 2;

    // ---- CSR build ----
    k_zero<<<(N + 255) / 256, 256>>>(N);
    k_count<<<(E + 255) / 256, 256>>>(ei, E, N);
    k_scan<<<1, 1024>>>(N);
    k_nodeprep<<<(N + 255) / 256, 256>>>(N);
    k_fill<<<(E + 255) / 256, 256>>>(ei, E, N);

    dim3 blk(256);
    int rowBlocks = (N + 63) / 64;

    // ---- layer 1: p = x@W1l, q = x@W1r ----
    k_gemm_x<<<dim3(F1 / 64, rowBlocks), blk>>>(x, W1l, 0, N);
    k_gemm_x<<<dim3(F1 / 64, rowBlocks), blk>>>(x, W1r, 1, N);
    k_agg1<<<N, F1>>>(b1l);

    // ---- layer 2: u = h@W2l, v = h@W2r (aggregate post-projection: 64-wide) ----
    k_gemm_h<<<dim3(F2 / 64, rowBlocks), blk>>>(W2l, 0, N);
    k_gemm_h<<<dim3(F2 / 64, rowBlocks), blk>>>(W2r, 1, N);
    k_agg2<<<N, F2>>>(b2l);

    // ---- GCN: xw = z@Wg, then normalized aggregation with self loops ----
    k_gemm_z<<<dim3(F2 / 64, rowBlocks), blk>>>(Wg, N);
    k_agg3<<<N, F2>>>(bg, out);
}

// round 10
// speedup vs baseline: 1.5400x; 1.5400x over previous
#include <cuda_runtime.h>

#define NMAX 50000
#define EMAX 800000
#define F1 128
#define F2 64

// ---------------- scratch (static __device__ globals; no allocation) --------
__device__ int   g_cnt[NMAX];
__device__ int   g_cursor[NMAX];
__device__ int   g_rowptr[NMAX + 1];
__device__ int   g_bsum[64];
__device__ int   g_boff[64];
__device__ int   g_col[EMAX];
__device__ float g_dinv[NMAX];
__device__ float g_invcnt[NMAX];

__device__ float g_p [NMAX * F1];   // x @ W1l
__device__ float g_q [NMAX * F1];   // x @ W1r
__device__ float g_h [NMAX * F1];   // layer-1 output (relu)
__device__ float g_u [NMAX * F2];   // h @ W2l
__device__ float g_v [NMAX * F2];   // h @ W2r
__device__ float g_z [NMAX * F2];   // softmax output
__device__ float g_xw[NMAX * F2];   // z @ Wg

// ---------------- CSR build -------------------------------------------------
__global__ void k_zero(int n) {
    int i = blockIdx.x * blockDim.x + threadIdx.x;
    if (i < n) { g_cnt[i] = 0; g_cursor[i] = 0; }
}

__global__ void k_count(const int* __restrict__ ei, int E) {
    int e = blockIdx.x * blockDim.x + threadIdx.x;
    if (e < E) atomicAdd(&g_cnt[ei[E + e]], 1);
}

// phase 1: per-1024-chunk exclusive scan, chunk totals to g_bsum
__global__ void k_scan1(int n) {
    __shared__ int wsums[32];
    int tid = threadIdx.x;
    int i = blockIdx.x * 1024 + tid;
    int v = (i < n) ? g_cnt[i] : 0;
    int incl = v;
    #pragma unroll
    for (int off = 1; off < 32; off <<= 1) {
        int y = __shfl_up_sync(0xffffffffu, incl, off);
        if ((tid & 31) >= off) incl += y;
    }
    if ((tid & 31) == 31) wsums[tid >> 5] = incl;
    __syncthreads();
    if (tid < 32) {
        int w = wsums[tid];
        int wi = w;
        #pragma unroll
        for (int off = 1; off < 32; off <<= 1) {
            int y = __shfl_up_sync(0xffffffffu, wi, off);
            if (tid >= off) wi += y;
        }
        wsums[tid] = wi - w;   // exclusive warp offset
    }
    __syncthreads();
    int excl = wsums[tid >> 5] + incl - v;
    if (i < n) g_rowptr[i] = excl;
    if (tid == 1023) g_bsum[blockIdx.x] = excl + v;
}

// phase 2: serial scan of <=64 chunk totals (tiny)
__global__ void k_scan2(int nb, int n) {
    __shared__ int s[64];
    int tid = threadIdx.x;
    s[tid] = (tid < nb) ? g_bsum[tid] : 0;
    __syncthreads();
    if (tid == 0) {
        int acc = 0;
        for (int b = 0; b < nb; b++) { int t = s[b]; g_boff[b] = acc; acc += t; }
        g_rowptr[n] = acc;
    }
}

// phase 3: add chunk offsets
__global__ void k_scan3(int n) {
    int i = blockIdx.x * 1024 + threadIdx.x;
    if (i < n) g_rowptr[i] += g_boff[blockIdx.x];
}

__global__ void k_nodeprep(int n) {
    int i = blockIdx.x * blockDim.x + threadIdx.x;
    if (i < n) {
        int c = g_cnt[i];
        g_invcnt[i] = 1.0f / (float)(c > 1 ? c : 1);
        g_dinv[i]   = rsqrtf((float)(c + 1));   // GCN deg includes self-loop
    }
}

__global__ void k_fill(const int* __restrict__ ei, int E) {
    int e = blockIdx.x * blockDim.x + threadIdx.x;
    if (e < E) {
        int s = ei[e];
        int d = ei[E + e];
        int pos = atomicAdd(&g_cursor[d], 1);
        g_col[g_rowptr[d] + pos] = s;
    }
}

// ---------------- fused dual-B SGEMM ----------------------------------------
// C1[:, :MH] = A @ B1, C2[:, :MH] = A @ B2   (each B is [K, MH], row stride MH)
// Block column selects (B1,C1) or (B2,C2). BM=128, 8x8 microtile, float4 I/O.
template<int BN, int MH>
__device__ __forceinline__
void gemm_body(const float* __restrict__ A,
               const float* __restrict__ B1, const float* __restrict__ B2,
               float* __restrict__ C1, float* __restrict__ C2,
               int NR, int K) {
    constexpr int BM = 128, BK = 16, TM = 8, TN = 8;
    constexpr int NT = (BM / TM) * (BN / TN);
    __shared__ float As[BK][BM + 4];
    __shared__ float Bs[BK][BN];

    int tid = threadIdx.x;
    int tx = tid % (BN / TN);
    int ty = tid / (BN / TN);
    int rowBase = blockIdx.y * BM;
    int colBase = blockIdx.x * BN;

    const float* B; float* C; int cb;
    if (colBase < MH) { B = B1; C = C1; cb = colBase; }
    else              { B = B2; C = C2; cb = colBase - MH; }

    float acc[TM][TN];
    #pragma unroll
    for (int i = 0; i < TM; i++)
        #pragma unroll
        for (int j = 0; j < TN; j++) acc[i][j] = 0.f;

    for (int k0 = 0; k0 < K; k0 += BK) {
        // A tile: float4 global loads, transposed scalar smem stores
        #pragma unroll
        for (int i = tid; i < BM * BK / 4; i += NT) {
            int m  = i / (BK / 4);
            int kq = i % (BK / 4);
            float4 v = make_float4(0.f, 0.f, 0.f, 0.f);
            int r = rowBase + m;
            if (r < NR) v = *(const float4*)&A[(size_t)r * K + k0 + kq * 4];
            As[kq * 4 + 0][m] = v.x;
            As[kq * 4 + 1][m] = v.y;
            As[kq * 4 + 2][m] = v.z;
            As[kq * 4 + 3][m] = v.w;
        }
        // B tile: float4 straight through
        #pragma unroll
        for (int i = tid; i < BK * BN / 4; i += NT) {
            int k  = i / (BN / 4);
            int cq = i % (BN / 4);
            *(float4*)&Bs[k][cq * 4] =
                *(const float4*)&B[(size_t)(k0 + k) * MH + cb + cq * 4];
        }
        __syncthreads();
        #pragma unroll
        for (int kk = 0; kk < BK; kk++) {
            float4 a0 = *(const float4*)&As[kk][ty * TM];
            float4 a1 = *(const float4*)&As[kk][ty * TM + 4];
            float4 b0 = *(const float4*)&Bs[kk][tx * TN];
            float4 b1 = *(const float4*)&Bs[kk][tx * TN + 4];
            float a[TM] = {a0.x, a0.y, a0.z, a0.w, a1.x, a1.y, a1.z, a1.w};
            float b[TN] = {b0.x, b0.y, b0.z, b0.w, b1.x, b1.y, b1.z, b1.w};
            #pragma unroll
            for (int i = 0; i < TM; i++)
                #pragma unroll
                for (int j = 0; j < TN; j++)
                    acc[i][j] = fmaf(a[i], b[j], acc[i][j]);
        }
        __syncthreads();
    }
    #pragma unroll
    for (int i = 0; i < TM; i++) {
        int r = rowBase + ty * TM + i;
        if (r < NR) {
            float* cp = &C[(size_t)r * MH + cb + tx * TN];
            *(float4*)cp       = make_float4(acc[i][0], acc[i][1], acc[i][2], acc[i][3]);
            *(float4*)(cp + 4) = make_float4(acc[i][4], acc[i][5], acc[i][6], acc[i][7]);
        }
    }
}

__global__ __launch_bounds__(256)
void k_gemm1(const float* __restrict__ x, const float* __restrict__ W1l,
             const float* __restrict__ W1r, int NR) {
    gemm_body<128, 128>(x, W1l, W1r, g_p, g_q, NR, F1);
}
__global__ __launch_bounds__(128)
void k_gemm2(const float* __restrict__ W2l, const float* __restrict__ W2r, int NR) {
    gemm_body<64, 64>(g_h, W2l, W2r, g_u, g_v, NR, F1);
}
__global__ __launch_bounds__(128)
void k_gemm3(const float* __restrict__ Wg, int NR) {
    gemm_body<64, 64>(g_z, Wg, Wg, g_xw, g_xw, NR, F2);
}

// ---------------- aggregation kernels ---------------------------------------
__device__ __forceinline__ float4 f4add(float4 a, float4 b) {
    return make_float4(a.x + b.x, a.y + b.y, a.z + b.z, a.w + b.w);
}

// layer 1: warp per node, float4 lanes (32*4 = 128 feats)
// h = relu(agg(p)/cnt + b1l + q)
__global__ __launch_bounds__(256)
void k_agg1(const float* __restrict__ b1l, int n) {
    int node = blockIdx.x * 8 + (threadIdx.x >> 5);
    int lane = threadIdx.x & 31;
    if (node >= n) return;
    int beg = g_rowptr[node], end = g_rowptr[node + 1];
    const float4* P = (const float4*)g_p;
    float4 s = make_float4(0.f, 0.f, 0.f, 0.f);
    int e = beg;
    for (; e + 4 <= end; e += 4) {
        int j0 = g_col[e], j1 = g_col[e + 1], j2 = g_col[e + 2], j3 = g_col[e + 3];
        float4 a = P[(size_t)j0 * 32 + lane];
        float4 b = P[(size_t)j1 * 32 + lane];
        float4 c = P[(size_t)j2 * 32 + lane];
        float4 d = P[(size_t)j3 * 32 + lane];
        s = f4add(s, f4add(f4add(a, b), f4add(c, d)));
    }
    for (; e < end; e++)
        s = f4add(s, P[(size_t)g_col[e] * 32 + lane]);
    float ic = g_invcnt[node];
    float4 bb = ((const float4*)b1l)[lane];
    float4 qq = ((const float4*)g_q)[(size_t)node * 32 + lane];
    float4 h;
    h.x = fmaxf(s.x * ic + bb.x + qq.x, 0.f);
    h.y = fmaxf(s.y * ic + bb.y + qq.y, 0.f);
    h.z = fmaxf(s.z * ic + bb.z + qq.z, 0.f);
    h.w = fmaxf(s.w * ic + bb.w + qq.w, 0.f);
    ((float4*)g_h)[(size_t)node * 32 + lane] = h;
}

// layer 2: 16 lanes per node (16*4 = 64 feats), fused softmax
__global__ __launch_bounds__(256)
void k_agg2(const float* __restrict__ b2l, int n) {
    int node = blockIdx.x * 16 + (threadIdx.x >> 4);
    int sub  = threadIdx.x & 15;
    if (node >= n) return;
    int beg = g_rowptr[node], end = g_rowptr[node + 1];
    const float4* U = (const float4*)g_u;
    float4 s = make_float4(0.f, 0.f, 0.f, 0.f);
    int e = beg;
    for (; e + 4 <= end; e += 4) {
        int j0 = g_col[e], j1 = g_col[e + 1], j2 = g_col[e + 2], j3 = g_col[e + 3];
        float4 a = U[(size_t)j0 * 16 + sub];
        float4 b = U[(size_t)j1 * 16 + sub];
        float4 c = U[(size_t)j2 * 16 + sub];
        float4 d = U[(size_t)j3 * 16 + sub];
        s = f4add(s, f4add(f4add(a, b), f4add(c, d)));
    }
    for (; e < end; e++)
        s = f4add(s, U[(size_t)g_col[e] * 16 + sub]);
    float ic = g_invcnt[node];
    float4 bb = ((const float4*)b2l)[sub];
    float4 vv = ((const float4*)g_v)[(size_t)node * 16 + sub];
    float4 t;
    t.x = s.x * ic + bb.x + vv.x;
    t.y = s.y * ic + bb.y + vv.y;
    t.z = s.z * ic + bb.z + vv.z;
    t.w = s.w * ic + bb.w + vv.w;

    float m = fmaxf(fmaxf(t.x, t.y), fmaxf(t.z, t.w));
    #pragma unroll
    for (int off = 8; off > 0; off >>= 1)
        m = fmaxf(m, __shfl_xor_sync(0xffffffffu, m, off));
    float4 ex;
    ex.x = expf(t.x - m); ex.y = expf(t.y - m);
    ex.z = expf(t.z - m); ex.w = expf(t.w - m);
    float sum = ex.x + ex.y + ex.z + ex.w;
    #pragma unroll
    for (int off = 8; off > 0; off >>= 1)
        sum += __shfl_xor_sync(0xffffffffu, sum, off);
    float inv = 1.0f / sum;
    float4 z = make_float4(ex.x * inv, ex.y * inv, ex.z * inv, ex.w * inv);
    ((float4*)g_z)[(size_t)node * 16 + sub] = z;
}

// GCN: out = dinv[i]*agg(dinv[j]*xw[j]) + dinv[i]^2*xw[i] + bg ; 16 lanes/node
__global__ __launch_bounds__(256)
void k_agg3(const float* __restrict__ bg, float* __restrict__ out, int n) {
    int node = blockIdx.x * 16 + (threadIdx.x >> 4);
    int sub  = threadIdx.x & 15;
    if (node >= n) return;
    int beg = g_rowptr[node], end = g_rowptr[node + 1];
    const float4* XW = (const float4*)g_xw;
    float4 s = make_float4(0.f, 0.f, 0.f, 0.f);
    int e = beg;
    for (; e + 4 <= end; e += 4) {
        int j0 = g_col[e], j1 = g_col[e + 1], j2 = g_col[e + 2], j3 = g_col[e + 3];
        float w0 = g_dinv[j0], w1 = g_dinv[j1], w2 = g_dinv[j2], w3 = g_dinv[j3];
        float4 a = XW[(size_t)j0 * 16 + sub];
        float4 b = XW[(size_t)j1 * 16 + sub];
        float4 c = XW[(size_t)j2 * 16 + sub];
        float4 d = XW[(size_t)j3 * 16 + sub];
        s.x += w0 * a.x + w1 * b.x + w2 * c.x + w3 * d.x;
        s.y += w0 * a.y + w1 * b.y + w2 * c.y + w3 * d.y;
        s.z += w0 * a.z + w1 * b.z + w2 * c.z + w3 * d.z;
        s.w += w0 * a.w + w1 * b.w + w2 * c.w + w3 * d.w;
    }
    for (; e < end; e++) {
        int j = g_col[e];
        float w = g_dinv[j];
        float4 a = XW[(size_t)j * 16 + sub];
        s.x += w * a.x; s.y += w * a.y; s.z += w * a.z; s.w += w * a.w;
    }
    float di = g_dinv[node];
    float d2 = di * di;
    float4 bb = ((const float4*)bg)[sub];
    float4 xw = XW[(size_t)node * 16 + sub];
    float4 o;
    o.x = di * s.x + d2 * xw.x + bb.x;
    o.y = di * s.y + d2 * xw.y + bb.y;
    o.z = di * s.z + d2 * xw.z + bb.z;
    o.w = di * s.w + d2 * xw.w + bb.w;
    ((float4*)out)[(size_t)node * 16 + sub] = o;
}

// ---------------- launch ----------------------------------------------------
extern "C" void kernel_launch(void* const* d_in, const int* in_sizes, int n_in,
                              void* d_out, int out_size) {
    const float* x   = (const float*)d_in[0];
    const int*   ei  = (const int*)d_in[1];      // int32 (JAX x64 disabled)
    const float* W1l = (const float*)d_in[2];
    const float* b1l = (const float*)d_in[3];
    const float* W1r = (const float*)d_in[4];
    const float* W2l = (const float*)d_in[5];
    const float* b2l = (const float*)d_in[6];
    const float* W2r = (const float*)d_in[7];
    const float* Wg  = (const float*)d_in[8];
    const float* bg  = (const float*)d_in[9];
    float* out = (float*)d_out;

    int N = in_sizes[0] / F1;
    int E = in_sizes[1] / 2;
    int nb = (N + 1023) / 1024;

    // ---- CSR build ----
    k_zero<<<(N + 255) / 256, 256>>>(N);
    k_count<<<(E + 255) / 256, 256>>>(ei, E);
    k_scan1<<<nb, 1024>>>(N);
    k_scan2<<<1, 64>>>(nb, N);
    k_scan3<<<nb, 1024>>>(N);
    k_nodeprep<<<(N + 255) / 256, 256>>>(N);
    k_fill<<<(E + 255) / 256, 256>>>(ei, E);

    int rowBlocks = (N + 127) / 128;

    // ---- layer 1: p = x@W1l, q = x@W1r (fused) ----
    k_gemm1<<<dim3(2, rowBlocks), 256>>>(x, W1l, W1r, N);
    k_agg1<<<(N + 7) / 8, 256>>>(b1l, N);

    // ---- layer 2: u = h@W2l, v = h@W2r (fused, post-projection agg) ----
    k_gemm2<<<dim3(2, rowBlocks), 128>>>(W2l, W2r, N);
    k_agg2<<<(N + 15) / 16, 256>>>(b2l, N);

    // ---- GCN: xw = z@Wg, normalized agg with self loops ----
    k_gemm3<<<dim3(1, rowBlocks), 128>>>(Wg, N);
    k_agg3<<<(N + 15) / 16, 256>>>(bg, out, N);
}